// round 15
// baseline (speedup 1.0000x reference)
#include <cuda_runtime.h>
#include <cuda_fp16.h>
#include <math.h>

#define PP 64
#define BB 2048
#define HH 128
#define NIN 2

constexpr long ENC_SZ = (long)BB * PP * HH;       // 16777216
constexpr long HN_SZ  = (long)PP * 2 * BB * HH;   // 33554432

constexpr int CHS        = 72;                 // halfs per row in chunk tiles (144B, ldsm conflict-free)
constexpr int TILE_H     = 128 * CHS;          // one chunk tile = 9216 halfs = 18432 B
constexpr int STG_STRIDE = 132;                // fp32 gate-staging stride (>=128!)

// fp16 scratch (static device arrays -- allocation-free per harness rules)
__device__ __half g_h0h[(long)PP * 2 * BB * HH];   // h0 both layers, fp16
__device__ __half g_h1h[(long)PP * BB * HH];       // layer-0 output h1, fp16
__device__ __half g_w0[512 * 128];                 // permuted Whh0
__device__ __half g_w1[512 * 256];                 // permuted [Wih1 | Whh1]

__device__ __forceinline__ float tanha(float x) {
    float y; asm("tanh.approx.f32 %0, %1;" : "=f"(y) : "f"(x)); return y;
}
__device__ __forceinline__ float sigf(float x) { return 0.5f * tanha(0.5f * x) + 0.5f; }

__device__ __forceinline__ unsigned sptr(const void* p) {
    return (unsigned)__cvta_generic_to_shared(p);
}
__device__ __forceinline__ void cp16(unsigned s, const void* g) {
    asm volatile("cp.async.cg.shared.global [%0], [%1], 16;\n" :: "r"(s), "l"(g));
}
__device__ __forceinline__ void cp_commit() {
    asm volatile("cp.async.commit_group;\n" ::: "memory");
}
__device__ __forceinline__ void ldsm4(unsigned& r0, unsigned& r1, unsigned& r2, unsigned& r3,
                                      const void* p) {
    asm volatile("ldmatrix.sync.aligned.m8n8.x4.shared.b16 {%0,%1,%2,%3}, [%4];\n"
                 : "=r"(r0), "=r"(r1), "=r"(r2), "=r"(r3)
                 : "r"(sptr(p)));
}

// ---- pre-pass: fp32 -> fp16 conversions (h0 full, W permuted) ----
__global__ __launch_bounds__(256) void prep(
    const float* __restrict__ h0,
    const float* __restrict__ Whh0,
    const float* __restrict__ Wih1,
    const float* __restrict__ Whh1)
{
    const long stride = (long)gridDim.x * blockDim.x;
    const long tid = (long)blockIdx.x * blockDim.x + threadIdx.x;

    const long n4 = (long)PP * 2 * BB * HH / 4;
    for (long i = tid; i < n4; i += stride) {
        float4 v = ((const float4*)h0)[i];
        ((__half2*)g_h0h)[2 * i]     = __floats2half2_rn(v.x, v.y);
        ((__half2*)g_h0h)[2 * i + 1] = __floats2half2_rn(v.z, v.w);
    }
    for (long i = tid; i < 512 * 128; i += stride) {
        int pr = (int)(i >> 7), k = (int)(i & 127);
        int nb = pr >> 7, np = pr & 127;
        int norig = (np & 3) * 128 + nb * 32 + (np >> 2);
        g_w0[i] = __float2half_rn(Whh0[norig * 128 + k]);
    }
    for (long i = tid; i < 512 * 256; i += stride) {
        int pr = (int)(i >> 8), k = (int)(i & 255);
        int nb = pr >> 7, np = pr & 127;
        int norig = (np & 3) * 128 + nb * 32 + (np >> 2);
        float v = (k < 128) ? Wih1[norig * 128 + k] : Whh1[norig * 128 + (k - 128)];
        g_w1[i] = __float2half_rn(v);
    }
}

// LSTM layer: fp16 mma.sync m16n8k16 GEMM, K=64 A+W chunks through a ring-2
// cp.async pipeline (one barrier per chunk), m64xn32 warp tiles, vectorized
// fused cell epilogue. Gate columns permuted (np = unit*4 + gate).
template <int LAYER>
__global__ __launch_bounds__(256, 2) void lstm_layer(
    const float* __restrict__ xin,
    const float* __restrict__ c0,
    const float* __restrict__ Wih0,
    const float* __restrict__ bih0,
    const float* __restrict__ bhh0,
    const float* __restrict__ bih1,
    const float* __restrict__ bhh1,
    float* __restrict__ dout)
{
    constexpr int NC = (LAYER == 0) ? 2 : 4;   // 64-wide K chunks (K=128 or 256)
    constexpr int KT = (LAYER == 0) ? 128 : 256;

    extern __shared__ __align__(16) unsigned char smem_raw[];
    float*  bsum   = (float*)smem_raw;                    // 128 permuted bias sums
    __half* chunks = (__half*)(smem_raw + 512);           // 2 buf x (A tile + W tile)

    const int tid  = threadIdx.x;
    const int lane = tid & 31;
    const int wid  = tid >> 5;
    const int grp  = lane >> 2;
    const int t4   = lane & 3;
    const int warpM = wid & 1;       // 2 warps along M: m64 each
    const int warpN = wid >> 1;      // 4 warps along N: n32 each

    const int nb = blockIdx.x;       // units [nb*32, nb*32+32)
    const int mb = blockIdx.y;       // 1024 m-blocks of 128 rows
    const int p  = mb >> 4;
    const int b0 = (mb & 15) * 128;

    const float* bi = LAYER ? bih1 : bih0;
    const float* bh = LAYER ? bhh1 : bhh0;
    if (tid < 128) {
        int g = tid & 3, u = tid >> 2, j = nb * 32 + u;
        bsum[tid] = bi[g * HH + j] + bh[g * HH + j];
    }

    float acc[4][4][4];
    #pragma unroll
    for (int i = 0; i < 4; i++)
        #pragma unroll
        for (int j = 0; j < 4; j++)
            #pragma unroll
            for (int k = 0; k < 4; k++) acc[i][j][k] = 0.f;

    const __half* gw = LAYER ? g_w1 : g_w0;

    auto load_chunk = [&](int c) {
        const __half* Ah;
        int kkA;
        if (LAYER == 0) {
            Ah = g_h0h + ((long)(p * 2) * BB + b0) * HH;  kkA = c * 64;
        } else if (c < 2) {
            Ah = g_h1h + ((long)p * BB + b0) * HH;        kkA = c * 64;
        } else {
            Ah = g_h0h + ((long)(p * 2 + 1) * BB + b0) * HH; kkA = (c - 2) * 64;
        }
        const int kkW = c * 64;
        __half* buf = chunks + (c & 1) * 2 * TILE_H;
        // A chunk: 128 rows x 64 k (8 x 16B per row)
        #pragma unroll
        for (int it = 0; it < 4; it++) {
            int idx = it * 256 + tid;
            int row = idx >> 3, q = idx & 7;
            cp16(sptr(buf + row * CHS + q * 8), Ah + (long)row * HH + kkA + q * 8);
        }
        // W chunk: 128 permuted gate-cols x 64 k
        #pragma unroll
        for (int it = 0; it < 4; it++) {
            int idx = it * 256 + tid;
            int np = idx >> 3, q = idx & 7;
            cp16(sptr(buf + TILE_H + np * CHS + q * 8),
                 gw + (long)(nb * 128 + np) * KT + kkW + q * 8);
        }
        cp_commit();
    };

    load_chunk(0);

    for (int c = 0; c < NC; c++) {
        // wait chunk c; this barrier also proves all warps finished chunk c-1,
        // so buf[(c+1)&1] is safe to refill below. One barrier per chunk.
        asm volatile("cp.async.wait_group 0;" ::: "memory");
        __syncthreads();
        if (c + 1 < NC) load_chunk(c + 1);

        const __half* Ab = chunks + (c & 1) * 2 * TILE_H;
        const __half* Wb = Ab + TILE_H;

        #pragma unroll
        for (int ks = 0; ks < 4; ks++) {
            const int kk = ks * 16;
            unsigned a[4][4];
            #pragma unroll
            for (int mt = 0; mt < 4; mt++) {
                const int R = warpM * 64 + mt * 16;
                const __half* pa = Ab + (R + (lane & 15)) * CHS + kk + ((lane >> 4) << 3);
                ldsm4(a[mt][0], a[mt][1], a[mt][2], a[mt][3], pa);
            }
            unsigned b0r[4], b1r[4];
            {
                const int C = warpN * 32;
                const __half* pb0 = Wb + (C + lane) * CHS + kk;
                ldsm4(b0r[0], b0r[1], b0r[2], b0r[3], pb0);
                const __half* pb1 = Wb + (C + lane) * CHS + kk + 8;
                ldsm4(b1r[0], b1r[1], b1r[2], b1r[3], pb1);
            }
            #pragma unroll
            for (int mt = 0; mt < 4; mt++) {
                #pragma unroll
                for (int nt = 0; nt < 4; nt++) {
                    asm volatile(
                        "mma.sync.aligned.m16n8k16.row.col.f32.f16.f16.f32 "
                        "{%0,%1,%2,%3}, {%4,%5,%6,%7}, {%8,%9}, {%0,%1,%2,%3};\n"
                        : "+f"(acc[mt][nt][0]), "+f"(acc[mt][nt][1]),
                          "+f"(acc[mt][nt][2]), "+f"(acc[mt][nt][3])
                        : "r"(a[mt][0]), "r"(a[mt][1]), "r"(a[mt][2]), "r"(a[mt][3]),
                          "r"(b0r[nt]), "r"(b1r[nt]));
                }
            }
        }
    }
    __syncthreads();   // all warps done reading final chunk before staging

    // ---- stage gates (fp32) into the dead chunk buffers, stride 132 ----
    float* sG = (float*)chunks;     // 128*132*4 = 67584 B <= 73728 B of ring
    #pragma unroll
    for (int mt = 0; mt < 4; mt++) {
        #pragma unroll
        for (int nt = 0; nt < 4; nt++) {
            int r   = warpM * 64 + mt * 16 + grp;
            int col = warpN * 32 + nt * 8 + t4 * 2;
            sG[r * STG_STRIDE + col]           = acc[mt][nt][0];
            sG[r * STG_STRIDE + col + 1]       = acc[mt][nt][1];
            sG[(r + 8) * STG_STRIDE + col]     = acc[mt][nt][2];
            sG[(r + 8) * STG_STRIDE + col + 1] = acc[mt][nt][3];
        }
    }
    __syncthreads();

    // ---- fused LSTM cell epilogue, 4 units per thread (float4 I/O) ----
    float* out_enc = dout;
    float* out_h   = dout + ENC_SZ;
    float* out_c   = dout + ENC_SZ + HN_SZ;

    #pragma unroll
    for (int it = 0; it < 4; it++) {
        int w = it * 256 + tid;          // 1024 items: 128 rows x 8 unit-quads
        int ml = w >> 3, q4 = w & 7;
        int b  = b0 + ml;
        int j0l = q4 * 4;                // local unit 0..28
        int j  = nb * 32 + j0l;

        const float* gr = sG + ml * STG_STRIDE + j0l * 4;
        float4 g4u[4];
        g4u[0] = *(const float4*)(gr);
        g4u[1] = *(const float4*)(gr + 4);
        g4u[2] = *(const float4*)(gr + 8);
        g4u[3] = *(const float4*)(gr + 12);
        float4 bs4[4];
        bs4[0] = *(const float4*)(bsum + j0l * 4);
        bs4[1] = *(const float4*)(bsum + j0l * 4 + 4);
        bs4[2] = *(const float4*)(bsum + j0l * 4 + 8);
        bs4[3] = *(const float4*)(bsum + j0l * 4 + 12);

        const long sidx = ((long)(p * 2 + LAYER) * BB + b) * HH + j;
        const float4 cp4 = *(const float4*)(c0 + sidx);
        const float cpv[4] = {cp4.x, cp4.y, cp4.z, cp4.w};

        float2 x2 = make_float2(0.f, 0.f);
        float4 wgi[2], wgf[2], wgg[2], wgo[2];   // Wih0 rows for 4 units (8 floats/gate)
        if (LAYER == 0) {
            x2 = *(const float2*)(xin + ((long)b * PP + p) * NIN);
            wgi[0] = *(const float4*)(Wih0 + (0 * HH + j) * NIN);
            wgi[1] = *(const float4*)(Wih0 + (0 * HH + j) * NIN + 4);
            wgf[0] = *(const float4*)(Wih0 + (1 * HH + j) * NIN);
            wgf[1] = *(const float4*)(Wih0 + (1 * HH + j) * NIN + 4);
            wgg[0] = *(const float4*)(Wih0 + (2 * HH + j) * NIN);
            wgg[1] = *(const float4*)(Wih0 + (2 * HH + j) * NIN + 4);
            wgo[0] = *(const float4*)(Wih0 + (3 * HH + j) * NIN);
            wgo[1] = *(const float4*)(Wih0 + (3 * HH + j) * NIN + 4);
        }

        float hv[4], cv[4];
        #pragma unroll
        for (int u = 0; u < 4; u++) {
            float gi = g4u[u].x + bs4[u].x;
            float gf = g4u[u].y + bs4[u].y;
            float gg = g4u[u].z + bs4[u].z;
            float go = g4u[u].w + bs4[u].w;
            if (LAYER == 0) {
                const float* wiu = ((const float*)wgi) + u * 2;
                const float* wfu = ((const float*)wgf) + u * 2;
                const float* wgu = ((const float*)wgg) + u * 2;
                const float* wou = ((const float*)wgo) + u * 2;
                gi += x2.x * wiu[0] + x2.y * wiu[1];
                gf += x2.x * wfu[0] + x2.y * wfu[1];
                gg += x2.x * wgu[0] + x2.y * wgu[1];
                go += x2.x * wou[0] + x2.y * wou[1];
            }
            const float cn = sigf(gf) * cpv[u] + sigf(gi) * tanha(gg);
            cv[u] = cn;
            hv[u] = sigf(go) * tanha(cn);
        }

        *(float4*)(out_h + sidx) = make_float4(hv[0], hv[1], hv[2], hv[3]);
        *(float4*)(out_c + sidx) = make_float4(cv[0], cv[1], cv[2], cv[3]);
        if (LAYER == 0) {
            __half2* dh = (__half2*)(g_h1h + ((long)p * BB + b) * HH + j);
            dh[0] = __floats2half2_rn(hv[0], hv[1]);
            dh[1] = __floats2half2_rn(hv[2], hv[3]);
        } else {
            *(float4*)(out_enc + ((long)b * PP + p) * HH + j) =
                make_float4(hv[0], hv[1], hv[2], hv[3]);
        }
    }
}

extern "C" void kernel_launch(void* const* d_in, const int* in_sizes, int n_in,
                              void* d_out, int out_size)
{
    const float* xin  = (const float*)d_in[0];
    const float* h0   = (const float*)d_in[1];
    const float* c0   = (const float*)d_in[2];
    const float* Wih0 = (const float*)d_in[3];
    const float* Whh0 = (const float*)d_in[4];
    const float* bih0 = (const float*)d_in[5];
    const float* bhh0 = (const float*)d_in[6];
    const float* Wih1 = (const float*)d_in[7];
    const float* Whh1 = (const float*)d_in[8];
    const float* bih1 = (const float*)d_in[9];
    const float* bhh1 = (const float*)d_in[10];
    float* dout = (float*)d_out;

    // smem: 512B bias + 2 ring buffers x (A+W) x 18432B = 74240 B -> 2 CTAs/SM
    const int smem_bytes = 512 + 4 * TILE_H * (int)sizeof(__half);

    cudaFuncSetAttribute(lstm_layer<0>, cudaFuncAttributeMaxDynamicSharedMemorySize, smem_bytes);
    cudaFuncSetAttribute(lstm_layer<1>, cudaFuncAttributeMaxDynamicSharedMemorySize, smem_bytes);

    prep<<<1024, 256>>>(h0, Whh0, Wih1, Whh1);

    dim3 grid(4, 1024);   // 4 n-blocks x 1024 m-blocks
    lstm_layer<0><<<grid, 256, smem_bytes>>>(xin, c0, Wih0, bih0, bhh0, bih1, bhh1, dout);
    lstm_layer<1><<<grid, 256, smem_bytes>>>(xin, c0, Wih0, bih0, bhh0, bih1, bhh1, dout);
}

// round 16
// speedup vs baseline: 1.0821x; 1.0821x over previous
#include <cuda_runtime.h>
#include <cuda_fp16.h>
#include <math.h>

#define PP 64
#define BB 2048
#define HH 128
#define NIN 2

constexpr long ENC_SZ = (long)BB * PP * HH;       // 16777216
constexpr long HN_SZ  = (long)PP * 2 * BB * HH;   // 33554432

constexpr int CHS        = 72;                 // halfs per row in chunk tiles (144B, ldsm conflict-free)
constexpr int TILE_H     = 128 * CHS;          // one chunk tile = 9216 halfs = 18432 B
constexpr int STG_STRIDE = 132;                // fp32 gate-staging stride

// fp16 scratch (static device arrays -- allocation-free per harness rules)
__device__ __half g_h0h[(long)PP * 2 * BB * HH];   // h0 both layers, fp16
__device__ __half g_h1h[(long)PP * BB * HH];       // layer-0 output h1, fp16
__device__ __half g_w0[512 * 128];                 // permuted Whh0
__device__ __half g_w1[512 * 256];                 // permuted [Wih1 | Whh1]

__device__ __forceinline__ float tanha(float x) {
    float y; asm("tanh.approx.f32 %0, %1;" : "=f"(y) : "f"(x)); return y;
}
__device__ __forceinline__ float sigf(float x) { return 0.5f * tanha(0.5f * x) + 0.5f; }

__device__ __forceinline__ unsigned sptr(const void* p) {
    return (unsigned)__cvta_generic_to_shared(p);
}
__device__ __forceinline__ void cp16(unsigned s, const void* g) {
    asm volatile("cp.async.cg.shared.global [%0], [%1], 16;\n" :: "r"(s), "l"(g));
}
__device__ __forceinline__ void cp_commit() {
    asm volatile("cp.async.commit_group;\n" ::: "memory");
}
__device__ __forceinline__ void ldsm4(unsigned& r0, unsigned& r1, unsigned& r2, unsigned& r3,
                                      const void* p) {
    asm volatile("ldmatrix.sync.aligned.m8n8.x4.shared.b16 {%0,%1,%2,%3}, [%4];\n"
                 : "=r"(r0), "=r"(r1), "=r"(r2), "=r"(r3)
                 : "r"(sptr(p)));
}

// ---- pre-pass: h0 LAYER-0 slices only (fp32 -> fp16) + W permuted ----
__global__ __launch_bounds__(256) void prep(
    const float* __restrict__ h0,
    const float* __restrict__ Whh0,
    const float* __restrict__ Wih1,
    const float* __restrict__ Whh1)
{
    const long stride = (long)gridDim.x * blockDim.x;
    const long tid = (long)blockIdx.x * blockDim.x + threadIdx.x;

    const long SL4 = (long)BB * HH / 4;          // float4s per (p, layer) slice
    for (long i = tid; i < (long)PP * SL4; i += stride) {
        long p = i / SL4, r = i - p * SL4;
        long si = (p * 2) * SL4 + r;             // layer-0 slice of pedestrian p
        float4 v = ((const float4*)h0)[si];
        ((__half2*)g_h0h)[2 * si]     = __floats2half2_rn(v.x, v.y);
        ((__half2*)g_h0h)[2 * si + 1] = __floats2half2_rn(v.z, v.w);
    }
    for (long i = tid; i < 512 * 128; i += stride) {
        int pr = (int)(i >> 7), k = (int)(i & 127);
        int nb = pr >> 7, np = pr & 127;
        int norig = (np & 3) * 128 + nb * 32 + (np >> 2);
        g_w0[i] = __float2half_rn(Whh0[norig * 128 + k]);
    }
    for (long i = tid; i < 512 * 256; i += stride) {
        int pr = (int)(i >> 8), k = (int)(i & 255);
        int nb = pr >> 7, np = pr & 127;
        int norig = (np & 3) * 128 + nb * 32 + (np >> 2);
        float v = (k < 128) ? Wih1[norig * 128 + k] : Whh1[norig * 128 + (k - 128)];
        g_w1[i] = __float2half_rn(v);
    }
}

// LSTM layer: fp16 mma.sync m16n8k16 GEMM, K=64 double-buffered cp.async chunks,
// m64xn32 warp tiles, fused cell epilogue. Gate columns permuted (np = unit*4+gate).
// (Mainloop + epilogue byte-identical to the 284us R7 kernel.)
// LAYER==0 additionally converts h0's layer-1 slices fp32->fp16 in a tail loop
// (consumed by the LAYER==1 kernel launch -- ordering via kernel boundary).
template <int LAYER>
__global__ __launch_bounds__(256, 2) void lstm_layer(
    const float* __restrict__ xin,
    const float* __restrict__ h0,
    const float* __restrict__ c0,
    const float* __restrict__ Wih0,
    const float* __restrict__ bih0,
    const float* __restrict__ bhh0,
    const float* __restrict__ bih1,
    const float* __restrict__ bhh1,
    float* __restrict__ dout)
{
    constexpr int NC = (LAYER == 0) ? 2 : 4;   // 64-wide K chunks (K=128 or 256)
    constexpr int KT = (LAYER == 0) ? 128 : 256;

    extern __shared__ __align__(16) unsigned char smem_raw[];
    float*  bsum   = (float*)smem_raw;                    // 128 permuted bias sums
    __half* chunks = (__half*)(smem_raw + 512);           // 2 buf x (A tile + W tile)

    const int tid  = threadIdx.x;
    const int lane = tid & 31;
    const int wid  = tid >> 5;
    const int grp  = lane >> 2;
    const int t4   = lane & 3;
    const int warpM = wid & 1;       // 2 warps along M: m64 each
    const int warpN = wid >> 1;      // 4 warps along N: n32 each

    const int nb = blockIdx.x;       // units [nb*32, nb*32+32)
    const int mb = blockIdx.y;       // 1024 m-blocks of 128 rows
    const int p  = mb >> 4;
    const int b0 = (mb & 15) * 128;

    const float* bi = LAYER ? bih1 : bih0;
    const float* bh = LAYER ? bhh1 : bhh0;
    if (tid < 128) {
        int g = tid & 3, u = tid >> 2, j = nb * 32 + u;
        bsum[tid] = bi[g * HH + j] + bh[g * HH + j];
    }

    float acc[4][4][4];
    #pragma unroll
    for (int i = 0; i < 4; i++)
        #pragma unroll
        for (int j = 0; j < 4; j++)
            #pragma unroll
            for (int k = 0; k < 4; k++) acc[i][j][k] = 0.f;

    const __half* gw = LAYER ? g_w1 : g_w0;

    auto load_chunk = [&](int c) {
        const __half* Ah;
        int kkA;
        if (LAYER == 0) {
            Ah = g_h0h + ((long)(p * 2) * BB + b0) * HH;  kkA = c * 64;
        } else if (c < 2) {
            Ah = g_h1h + ((long)p * BB + b0) * HH;        kkA = c * 64;
        } else {
            Ah = g_h0h + ((long)(p * 2 + 1) * BB + b0) * HH; kkA = (c - 2) * 64;
        }
        const int kkW = c * 64;
        __half* buf = chunks + (c & 1) * 2 * TILE_H;
        // A chunk: 128 rows x 64 k (8 x 16B per row)
        #pragma unroll
        for (int it = 0; it < 4; it++) {
            int idx = it * 256 + tid;
            int row = idx >> 3, q = idx & 7;
            cp16(sptr(buf + row * CHS + q * 8), Ah + (long)row * HH + kkA + q * 8);
        }
        // W chunk: 128 permuted gate-cols x 64 k
        #pragma unroll
        for (int it = 0; it < 4; it++) {
            int idx = it * 256 + tid;
            int np = idx >> 3, q = idx & 7;
            cp16(sptr(buf + TILE_H + np * CHS + q * 8),
                 gw + (long)(nb * 128 + np) * KT + kkW + q * 8);
        }
        cp_commit();
    };

    load_chunk(0);

    for (int c = 0; c < NC; c++) {
        if (c + 1 < NC) load_chunk(c + 1);
        if (c + 1 < NC) asm volatile("cp.async.wait_group 1;" ::: "memory");
        else            asm volatile("cp.async.wait_group 0;" ::: "memory");
        __syncthreads();

        const __half* Ab = chunks + (c & 1) * 2 * TILE_H;
        const __half* Wb = Ab + TILE_H;

        #pragma unroll
        for (int ks = 0; ks < 4; ks++) {
            const int kk = ks * 16;
            unsigned a[4][4];
            #pragma unroll
            for (int mt = 0; mt < 4; mt++) {
                const int R = warpM * 64 + mt * 16;
                const __half* pa = Ab + (R + (lane & 15)) * CHS + kk + ((lane >> 4) << 3);
                ldsm4(a[mt][0], a[mt][1], a[mt][2], a[mt][3], pa);
            }
            unsigned b0r[4], b1r[4];
            {
                const int C = warpN * 32;
                const __half* pb0 = Wb + (C + lane) * CHS + kk;
                ldsm4(b0r[0], b0r[1], b0r[2], b0r[3], pb0);
                const __half* pb1 = Wb + (C + lane) * CHS + kk + 8;
                ldsm4(b1r[0], b1r[1], b1r[2], b1r[3], pb1);
            }
            #pragma unroll
            for (int mt = 0; mt < 4; mt++) {
                #pragma unroll
                for (int nt = 0; nt < 4; nt++) {
                    asm volatile(
                        "mma.sync.aligned.m16n8k16.row.col.f32.f16.f16.f32 "
                        "{%0,%1,%2,%3}, {%4,%5,%6,%7}, {%8,%9}, {%0,%1,%2,%3};\n"
                        : "+f"(acc[mt][nt][0]), "+f"(acc[mt][nt][1]),
                          "+f"(acc[mt][nt][2]), "+f"(acc[mt][nt][3])
                        : "r"(a[mt][0]), "r"(a[mt][1]), "r"(a[mt][2]), "r"(a[mt][3]),
                          "r"(b0r[nt]), "r"(b1r[nt]));
                }
            }
        }
        __syncthreads();   // buf[c&1] free for load(c+2)
    }

    // ---- stage gates (fp32) into the dead chunk buffers ----
    float* sG = (float*)chunks;
    #pragma unroll
    for (int mt = 0; mt < 4; mt++) {
        #pragma unroll
        for (int nt = 0; nt < 4; nt++) {
            int r   = warpM * 64 + mt * 16 + grp;
            int col = warpN * 32 + nt * 8 + t4 * 2;
            sG[r * STG_STRIDE + col]           = acc[mt][nt][0];
            sG[r * STG_STRIDE + col + 1]       = acc[mt][nt][1];
            sG[(r + 8) * STG_STRIDE + col]     = acc[mt][nt][2];
            sG[(r + 8) * STG_STRIDE + col + 1] = acc[mt][nt][3];
        }
    }
    __syncthreads();

    // ---- fused LSTM cell epilogue ----
    float* out_enc = dout;
    float* out_h   = dout + ENC_SZ;
    float* out_c   = dout + ENC_SZ + HN_SZ;

    #pragma unroll
    for (int it = 0; it < 16; it++) {
        int cell = it * 256 + tid;        // 128 rows x 32 units
        int ml = cell >> 5, jl = cell & 31;
        int b = b0 + ml;
        int j = nb * 32 + jl;

        const float4 g4 = *(const float4*)(sG + ml * STG_STRIDE + jl * 4);
        const float4 bs = *(const float4*)(bsum + jl * 4);
        float gi = g4.x + bs.x;
        float gf = g4.y + bs.y;
        float gg = g4.z + bs.z;
        float go = g4.w + bs.w;

        if (LAYER == 0) {
            const float2 x2 = *(const float2*)(xin + ((long)b * PP + p) * NIN);
            const float2 wi = *(const float2*)(Wih0 + (0 * HH + j) * NIN);
            const float2 wf = *(const float2*)(Wih0 + (1 * HH + j) * NIN);
            const float2 wg = *(const float2*)(Wih0 + (2 * HH + j) * NIN);
            const float2 wo = *(const float2*)(Wih0 + (3 * HH + j) * NIN);
            gi += x2.x * wi.x + x2.y * wi.y;
            gf += x2.x * wf.x + x2.y * wf.y;
            gg += x2.x * wg.x + x2.y * wg.y;
            go += x2.x * wo.x + x2.y * wo.y;
        }

        const long sidx = ((long)(p * 2 + LAYER) * BB + b) * HH + j;
        const float cprev = c0[sidx];
        const float cn = sigf(gf) * cprev + sigf(gi) * tanha(gg);
        const float hn = sigf(go) * tanha(cn);

        out_h[sidx] = hn;
        out_c[sidx] = cn;
        if (LAYER == 0) {
            g_h1h[((long)p * BB + b) * HH + j] = __float2half_rn(hn);
        } else {
            out_enc[((long)b * PP + p) * HH + j] = hn;
        }
    }

    // ---- LAYER 0 tail: convert h0's layer-1 slices fp32 -> fp16 ----
    // (read by the LAYER==1 kernel launch; kernel boundary orders it)
    if (LAYER == 0) {
        const long SL4 = (long)BB * HH / 4;              // float4s per slice
        const long total = (long)PP * SL4;               // 4M float4
        const long gstride = (long)4 * 1024 * 256;       // grid threads
        long gt = ((long)blockIdx.y * 4 + blockIdx.x) * 256 + tid;
        for (long i = gt; i < total; i += gstride) {
            long pp = i / SL4, r = i - pp * SL4;
            long si = (pp * 2 + 1) * SL4 + r;            // layer-1 slice
            float4 v = ((const float4*)h0)[si];
            ((__half2*)g_h0h)[2 * si]     = __floats2half2_rn(v.x, v.y);
            ((__half2*)g_h0h)[2 * si + 1] = __floats2half2_rn(v.z, v.w);
        }
    }
}

extern "C" void kernel_launch(void* const* d_in, const int* in_sizes, int n_in,
                              void* d_out, int out_size)
{
    const float* xin  = (const float*)d_in[0];
    const float* h0   = (const float*)d_in[1];
    const float* c0   = (const float*)d_in[2];
    const float* Wih0 = (const float*)d_in[3];
    const float* Whh0 = (const float*)d_in[4];
    const float* bih0 = (const float*)d_in[5];
    const float* bhh0 = (const float*)d_in[6];
    const float* Wih1 = (const float*)d_in[7];
    const float* Whh1 = (const float*)d_in[8];
    const float* bih1 = (const float*)d_in[9];
    const float* bhh1 = (const float*)d_in[10];
    float* dout = (float*)d_out;

    // smem: 512B bias + 4 tiles x 18432B = 74240B total -> 2 CTAs/SM
    const int smem_bytes = 512 + 4 * TILE_H * (int)sizeof(__half);

    cudaFuncSetAttribute(lstm_layer<0>, cudaFuncAttributeMaxDynamicSharedMemorySize, smem_bytes);
    cudaFuncSetAttribute(lstm_layer<1>, cudaFuncAttributeMaxDynamicSharedMemorySize, smem_bytes);

    prep<<<1024, 256>>>(h0, Whh0, Wih1, Whh1);

    dim3 grid(4, 1024);   // 4 n-blocks x 1024 m-blocks
    lstm_layer<0><<<grid, 256, smem_bytes>>>(xin, h0, c0, Wih0, bih0, bhh0, bih1, bhh1, dout);
    lstm_layer<1><<<grid, 256, smem_bytes>>>(xin, h0, c0, Wih0, bih0, bhh0, bih1, bhh1, dout);
}

// round 17
// speedup vs baseline: 1.1351x; 1.0490x over previous
#include <cuda_runtime.h>
#include <cuda_fp16.h>
#include <math.h>

#define PP 64
#define BB 2048
#define HH 128
#define NIN 2

constexpr long ENC_SZ = (long)BB * PP * HH;       // 16777216
constexpr long HN_SZ  = (long)PP * 2 * BB * HH;   // 33554432

constexpr int CHS        = 72;                 // halfs per row in chunk tiles (144B, ldsm conflict-free)
constexpr int TILE_H     = 128 * CHS;          // one chunk tile = 9216 halfs = 18432 B
constexpr int STG_STRIDE = 132;                // fp32 gate-staging stride

// fp16 scratch (static device arrays -- allocation-free per harness rules)
__device__ __half g_h0h[(long)PP * 2 * BB * HH];   // h0 both layers, fp16
__device__ __half g_h1h[(long)PP * BB * HH];       // layer-0 output h1, fp16
__device__ __half g_w0[512 * 128];                 // permuted Whh0
__device__ __half g_w1[512 * 256];                 // permuted [Wih1 | Whh1]

__device__ __forceinline__ float tanha(float x) {
    float y; asm("tanh.approx.f32 %0, %1;" : "=f"(y) : "f"(x)); return y;
}
__device__ __forceinline__ float sigf(float x) { return 0.5f * tanha(0.5f * x) + 0.5f; }

__device__ __forceinline__ unsigned sptr(const void* p) {
    return (unsigned)__cvta_generic_to_shared(p);
}
__device__ __forceinline__ void cp16(unsigned s, const void* g) {
    asm volatile("cp.async.cg.shared.global [%0], [%1], 16;\n" :: "r"(s), "l"(g));
}
__device__ __forceinline__ void cp_commit() {
    asm volatile("cp.async.commit_group;\n" ::: "memory");
}
__device__ __forceinline__ void ldsm4(unsigned& r0, unsigned& r1, unsigned& r2, unsigned& r3,
                                      const void* p) {
    asm volatile("ldmatrix.sync.aligned.m8n8.x4.shared.b16 {%0,%1,%2,%3}, [%4];\n"
                 : "=r"(r0), "=r"(r1), "=r"(r2), "=r"(r3)
                 : "r"(sptr(p)));
}

// ---- pre-pass: fp32 -> fp16 conversions, ordered for L2 reuse:
// W first, then h0 layer-1 halves, then h0 layer-0 halves LAST so that
// layer-0's A input (67MB + W) is the freshest content in L2 at L0 launch. ----
__global__ __launch_bounds__(256) void prep(
    const float* __restrict__ h0,
    const float* __restrict__ Whh0,
    const float* __restrict__ Wih1,
    const float* __restrict__ Whh1)
{
    const long stride = (long)gridDim.x * blockDim.x;
    const long tid = (long)blockIdx.x * blockDim.x + threadIdx.x;

    for (long i = tid; i < 512 * 128; i += stride) {
        int pr = (int)(i >> 7), k = (int)(i & 127);
        int nb = pr >> 7, np = pr & 127;
        int norig = (np & 3) * 128 + nb * 32 + (np >> 2);
        g_w0[i] = __float2half_rn(Whh0[norig * 128 + k]);
    }
    for (long i = tid; i < 512 * 256; i += stride) {
        int pr = (int)(i >> 8), k = (int)(i & 255);
        int nb = pr >> 7, np = pr & 127;
        int norig = (np & 3) * 128 + nb * 32 + (np >> 2);
        float v = (k < 128) ? Wih1[norig * 128 + k] : Whh1[norig * 128 + (k - 128)];
        g_w1[i] = __float2half_rn(v);
    }

    const long SL4 = (long)BB * HH / 4;          // float4s per (p, layer) slice
    // h0 layer-1 halves first
    for (long i = tid; i < (long)PP * SL4; i += stride) {
        long p = i / SL4, r = i - p * SL4;
        long si = (p * 2 + 1) * SL4 + r;
        float4 v = ((const float4*)h0)[si];
        ((__half2*)g_h0h)[2 * si]     = __floats2half2_rn(v.x, v.y);
        ((__half2*)g_h0h)[2 * si + 1] = __floats2half2_rn(v.z, v.w);
    }
    // h0 layer-0 halves last (freshest in L2 for the L0 kernel)
    for (long i = tid; i < (long)PP * SL4; i += stride) {
        long p = i / SL4, r = i - p * SL4;
        long si = (p * 2) * SL4 + r;
        float4 v = ((const float4*)h0)[si];
        ((__half2*)g_h0h)[2 * si]     = __floats2half2_rn(v.x, v.y);
        ((__half2*)g_h0h)[2 * si + 1] = __floats2half2_rn(v.z, v.w);
    }
}

// LSTM layer: fp16 mma.sync m16n8k16 GEMM, K=64 double-buffered cp.async chunks,
// m64xn32 warp tiles, fused cell epilogue. Gate columns permuted (np = unit*4+gate).
// (Byte-identical to the 284us R7 kernel.)
template <int LAYER>
__global__ __launch_bounds__(256, 2) void lstm_layer(
    const float* __restrict__ xin,
    const float* __restrict__ c0,
    const float* __restrict__ Wih0,
    const float* __restrict__ bih0,
    const float* __restrict__ bhh0,
    const float* __restrict__ bih1,
    const float* __restrict__ bhh1,
    float* __restrict__ dout)
{
    constexpr int NC = (LAYER == 0) ? 2 : 4;   // 64-wide K chunks (K=128 or 256)
    constexpr int KT = (LAYER == 0) ? 128 : 256;

    extern __shared__ __align__(16) unsigned char smem_raw[];
    float*  bsum   = (float*)smem_raw;                    // 128 permuted bias sums
    __half* chunks = (__half*)(smem_raw + 512);           // 2 buf x (A tile + W tile)

    const int tid  = threadIdx.x;
    const int lane = tid & 31;
    const int wid  = tid >> 5;
    const int grp  = lane >> 2;
    const int t4   = lane & 3;
    const int warpM = wid & 1;       // 2 warps along M: m64 each
    const int warpN = wid >> 1;      // 4 warps along N: n32 each

    const int nb = blockIdx.x;       // units [nb*32, nb*32+32)
    const int mb = blockIdx.y;       // 1024 m-blocks of 128 rows
    const int p  = mb >> 4;
    const int b0 = (mb & 15) * 128;

    const float* bi = LAYER ? bih1 : bih0;
    const float* bh = LAYER ? bhh1 : bhh0;
    if (tid < 128) {
        int g = tid & 3, u = tid >> 2, j = nb * 32 + u;
        bsum[tid] = bi[g * HH + j] + bh[g * HH + j];
    }

    float acc[4][4][4];
    #pragma unroll
    for (int i = 0; i < 4; i++)
        #pragma unroll
        for (int j = 0; j < 4; j++)
            #pragma unroll
            for (int k = 0; k < 4; k++) acc[i][j][k] = 0.f;

    const __half* gw = LAYER ? g_w1 : g_w0;

    auto load_chunk = [&](int c) {
        const __half* Ah;
        int kkA;
        if (LAYER == 0) {
            Ah = g_h0h + ((long)(p * 2) * BB + b0) * HH;  kkA = c * 64;
        } else if (c < 2) {
            Ah = g_h1h + ((long)p * BB + b0) * HH;        kkA = c * 64;
        } else {
            Ah = g_h0h + ((long)(p * 2 + 1) * BB + b0) * HH; kkA = (c - 2) * 64;
        }
        const int kkW = c * 64;
        __half* buf = chunks + (c & 1) * 2 * TILE_H;
        // A chunk: 128 rows x 64 k (8 x 16B per row)
        #pragma unroll
        for (int it = 0; it < 4; it++) {
            int idx = it * 256 + tid;
            int row = idx >> 3, q = idx & 7;
            cp16(sptr(buf + row * CHS + q * 8), Ah + (long)row * HH + kkA + q * 8);
        }
        // W chunk: 128 permuted gate-cols x 64 k
        #pragma unroll
        for (int it = 0; it < 4; it++) {
            int idx = it * 256 + tid;
            int np = idx >> 3, q = idx & 7;
            cp16(sptr(buf + TILE_H + np * CHS + q * 8),
                 gw + (long)(nb * 128 + np) * KT + kkW + q * 8);
        }
        cp_commit();
    };

    load_chunk(0);

    for (int c = 0; c < NC; c++) {
        if (c + 1 < NC) load_chunk(c + 1);
        if (c + 1 < NC) asm volatile("cp.async.wait_group 1;" ::: "memory");
        else            asm volatile("cp.async.wait_group 0;" ::: "memory");
        __syncthreads();

        const __half* Ab = chunks + (c & 1) * 2 * TILE_H;
        const __half* Wb = Ab + TILE_H;

        #pragma unroll
        for (int ks = 0; ks < 4; ks++) {
            const int kk = ks * 16;
            unsigned a[4][4];
            #pragma unroll
            for (int mt = 0; mt < 4; mt++) {
                const int R = warpM * 64 + mt * 16;
                const __half* pa = Ab + (R + (lane & 15)) * CHS + kk + ((lane >> 4) << 3);
                ldsm4(a[mt][0], a[mt][1], a[mt][2], a[mt][3], pa);
            }
            unsigned b0r[4], b1r[4];
            {
                const int C = warpN * 32;
                const __half* pb0 = Wb + (C + lane) * CHS + kk;
                ldsm4(b0r[0], b0r[1], b0r[2], b0r[3], pb0);
                const __half* pb1 = Wb + (C + lane) * CHS + kk + 8;
                ldsm4(b1r[0], b1r[1], b1r[2], b1r[3], pb1);
            }
            #pragma unroll
            for (int mt = 0; mt < 4; mt++) {
                #pragma unroll
                for (int nt = 0; nt < 4; nt++) {
                    asm volatile(
                        "mma.sync.aligned.m16n8k16.row.col.f32.f16.f16.f32 "
                        "{%0,%1,%2,%3}, {%4,%5,%6,%7}, {%8,%9}, {%0,%1,%2,%3};\n"
                        : "+f"(acc[mt][nt][0]), "+f"(acc[mt][nt][1]),
                          "+f"(acc[mt][nt][2]), "+f"(acc[mt][nt][3])
                        : "r"(a[mt][0]), "r"(a[mt][1]), "r"(a[mt][2]), "r"(a[mt][3]),
                          "r"(b0r[nt]), "r"(b1r[nt]));
                }
            }
        }
        __syncthreads();   // buf[c&1] free for load(c+2)
    }

    // ---- stage gates (fp32) into the dead chunk buffers ----
    float* sG = (float*)chunks;
    #pragma unroll
    for (int mt = 0; mt < 4; mt++) {
        #pragma unroll
        for (int nt = 0; nt < 4; nt++) {
            int r   = warpM * 64 + mt * 16 + grp;
            int col = warpN * 32 + nt * 8 + t4 * 2;
            sG[r * STG_STRIDE + col]           = acc[mt][nt][0];
            sG[r * STG_STRIDE + col + 1]       = acc[mt][nt][1];
            sG[(r + 8) * STG_STRIDE + col]     = acc[mt][nt][2];
            sG[(r + 8) * STG_STRIDE + col + 1] = acc[mt][nt][3];
        }
    }
    __syncthreads();

    // ---- fused LSTM cell epilogue ----
    float* out_enc = dout;
    float* out_h   = dout + ENC_SZ;
    float* out_c   = dout + ENC_SZ + HN_SZ;

    #pragma unroll
    for (int it = 0; it < 16; it++) {
        int cell = it * 256 + tid;        // 128 rows x 32 units
        int ml = cell >> 5, jl = cell & 31;
        int b = b0 + ml;
        int j = nb * 32 + jl;

        const float4 g4 = *(const float4*)(sG + ml * STG_STRIDE + jl * 4);
        const float4 bs = *(const float4*)(bsum + jl * 4);
        float gi = g4.x + bs.x;
        float gf = g4.y + bs.y;
        float gg = g4.z + bs.z;
        float go = g4.w + bs.w;

        if (LAYER == 0) {
            const float2 x2 = *(const float2*)(xin + ((long)b * PP + p) * NIN);
            const float2 wi = *(const float2*)(Wih0 + (0 * HH + j) * NIN);
            const float2 wf = *(const float2*)(Wih0 + (1 * HH + j) * NIN);
            const float2 wg = *(const float2*)(Wih0 + (2 * HH + j) * NIN);
            const float2 wo = *(const float2*)(Wih0 + (3 * HH + j) * NIN);
            gi += x2.x * wi.x + x2.y * wi.y;
            gf += x2.x * wf.x + x2.y * wf.y;
            gg += x2.x * wg.x + x2.y * wg.y;
            go += x2.x * wo.x + x2.y * wo.y;
        }

        const long sidx = ((long)(p * 2 + LAYER) * BB + b) * HH + j;
        const float cprev = c0[sidx];
        const float cn = sigf(gf) * cprev + sigf(gi) * tanha(gg);
        const float hn = sigf(go) * tanha(cn);

        out_h[sidx] = hn;
        out_c[sidx] = cn;
        if (LAYER == 0) {
            g_h1h[((long)p * BB + b) * HH + j] = __float2half_rn(hn);
        } else {
            out_enc[((long)b * PP + p) * HH + j] = hn;
        }
    }
}

extern "C" void kernel_launch(void* const* d_in, const int* in_sizes, int n_in,
                              void* d_out, int out_size)
{
    const float* xin  = (const float*)d_in[0];
    const float* h0   = (const float*)d_in[1];
    const float* c0   = (const float*)d_in[2];
    const float* Wih0 = (const float*)d_in[3];
    const float* Whh0 = (const float*)d_in[4];
    const float* bih0 = (const float*)d_in[5];
    const float* bhh0 = (const float*)d_in[6];
    const float* Wih1 = (const float*)d_in[7];
    const float* Whh1 = (const float*)d_in[8];
    const float* bih1 = (const float*)d_in[9];
    const float* bhh1 = (const float*)d_in[10];
    float* dout = (float*)d_out;

    // smem: 512B bias + 4 tiles x 18432B = 74240B total -> 2 CTAs/SM
    const int smem_bytes = 512 + 4 * TILE_H * (int)sizeof(__half);

    cudaFuncSetAttribute(lstm_layer<0>, cudaFuncAttributeMaxDynamicSharedMemorySize, smem_bytes);
    cudaFuncSetAttribute(lstm_layer<1>, cudaFuncAttributeMaxDynamicSharedMemorySize, smem_bytes);

    prep<<<1024, 256>>>(h0, Whh0, Wih1, Whh1);

    dim3 grid(4, 1024);   // 4 n-blocks x 1024 m-blocks
    lstm_layer<0><<<grid, 256, smem_bytes>>>(xin, c0, Wih0, bih0, bhh0, bih1, bhh1, dout);
    lstm_layer<1><<<grid, 256, smem_bytes>>>(xin, c0, Wih0, bih0, bhh0, bih1, bhh1, dout);
}